// round 14
// baseline (speedup 1.0000x reference)
#include <cuda_runtime.h>
#include <cstdint>

#define TT 2048
#define BB 32
#define HH 256
#define G4H 1024
#define GRID_R 128
#define CPG 8          // CTAs per cluster/group
#define NGRP 16        // groups (2 batches each)

// ---------------- scratch (static device allocations; no cudaMalloc) ----------------
__device__ float g_xg[(size_t)TT * G4H * BB];     // [t][gate_row][b]  256 MB
__device__ float g_hs0[(size_t)TT * BB * HH];     // layer-0 hidden outputs, 64 MB
__device__ int g_len[BB];                         // normalized lengths (int32)

// ---------------- lengths normalization: handles int32 OR int64 input buffer ----------
__global__ void norm_lengths(const int* __restrict__ lenw)
{
    int i = threadIdx.x;            // 0..31
    int is64 = (lenw[1] == 0);
    int v = is64 ? lenw[2 * i] : lenw[i];
    g_len[i] = v;
}

// ---------------- input-projection GEMM: out[t][row][b] = X @ W^T + bias ----------------
// X: [T*B][256] row-major, W: [1024][256], out: [T][1024][32]
__global__ __launch_bounds__(256) void xg_gemm(const float* __restrict__ X,
                                               const float* __restrict__ W,
                                               const float* __restrict__ bias,
                                               float* __restrict__ out)
{
    __shared__ float xs[64][65];
    __shared__ float ws[64][65];
    const int tid = threadIdx.x;
    const int tx = tid & 15;        // tb quad
    const int ty = tid >> 4;        // row quad
    const int tb0 = blockIdx.x * 64;
    const int r0 = blockIdx.y * 64;
    const int lrow = tid >> 4;      // load row 0..15 (x4 passes)
    const int lkq = tid & 15;       // load k-quad

    float acc[4][4];
#pragma unroll
    for (int i = 0; i < 4; i++)
#pragma unroll
        for (int j = 0; j < 4; j++) acc[i][j] = 0.f;

    for (int kt = 0; kt < 256; kt += 64) {
#pragma unroll
        for (int p = 0; p < 4; p++) {
            int row = lrow + p * 16;
            float4 xv = *(const float4*)&X[(size_t)(tb0 + row) * 256 + kt + lkq * 4];
            xs[row][lkq * 4 + 0] = xv.x; xs[row][lkq * 4 + 1] = xv.y;
            xs[row][lkq * 4 + 2] = xv.z; xs[row][lkq * 4 + 3] = xv.w;
            float4 wv = *(const float4*)&W[(size_t)(r0 + row) * 256 + kt + lkq * 4];
            ws[row][lkq * 4 + 0] = wv.x; ws[row][lkq * 4 + 1] = wv.y;
            ws[row][lkq * 4 + 2] = wv.z; ws[row][lkq * 4 + 3] = wv.w;
        }
        __syncthreads();
#pragma unroll 8
        for (int k = 0; k < 64; k++) {
            float xf[4], wf[4];
#pragma unroll
            for (int j = 0; j < 4; j++) xf[j] = xs[tx * 4 + j][k];
#pragma unroll
            for (int i = 0; i < 4; i++) wf[i] = ws[ty * 4 + i][k];
#pragma unroll
            for (int i = 0; i < 4; i++)
#pragma unroll
                for (int j = 0; j < 4; j++) acc[i][j] += wf[i] * xf[j];
        }
        __syncthreads();
    }

    const int tbb = tb0 + tx * 4;
    const int t = tbb >> 5;
    const int b0 = tbb & 31;
#pragma unroll
    for (int i = 0; i < 4; i++) {
        int row = r0 + ty * 4 + i;
        float bv = bias[row];
        float4 v = make_float4(acc[i][0] + bv, acc[i][1] + bv, acc[i][2] + bv, acc[i][3] + bv);
        *(float4*)&out[(size_t)t * 32768 + row * 32 + b0] = v;
    }
}

// ---------------- cluster helpers ----------------
__device__ __forceinline__ uint32_t smem_u32(const void* p) {
    uint32_t a;
    asm("{ .reg .u64 t; cvta.to.shared.u64 t, %1; cvt.u32.u64 %0, t; }" : "=r"(a) : "l"(p));
    return a;
}
__device__ __forceinline__ void st_remote_f32(uint32_t laddr, int rank, float v) {
    uint32_t raddr;
    asm volatile("mapa.shared::cluster.u32 %0, %1, %2;" : "=r"(raddr) : "r"(laddr), "r"(rank));
    asm volatile("st.shared::cluster.f32 [%0], %1;" :: "r"(raddr), "f"(v) : "memory");
}
#define CLUSTER_ARRIVE() asm volatile("barrier.cluster.arrive.aligned;" ::: "memory")
#define CLUSTER_WAIT()   asm volatile("barrier.cluster.wait.aligned;"   ::: "memory")

// ---------------- persistent recurrent kernel: CLUSTER + DSMEM exchange ----------------
// 128 CTAs = 16 clusters x 8 CTAs. Cluster (group) g owns batches {2g, 2g+1}. CTA r
// holds W_hh rows {256*G + 32*r + jj} in smem and computes those 128 gate rows for
// both batches. h state is replicated in every CTA's smem (double-buffered); owners
// push h_new into all 8 CTAs via DSMEM stores; barrier.cluster (release/acquire)
// orders writes->reads. No global counters, no reset state, no L2 exchange.
__global__ __launch_bounds__(256) __cluster_dims__(CPG, 1, 1)
void lstm_rec(
    const float* __restrict__ h0,        // [B][H] slice for this layer
    const float* __restrict__ c0,
    const float* __restrict__ Whh,       // [1024][256]
    float* __restrict__ hs_out,          // [T][B][H]
    float* __restrict__ cs_out,          // [T][B][H] or nullptr
    float* __restrict__ hT_out,          // [B][H]
    float* __restrict__ cT_out)
{
    extern __shared__ float smem[];
    // layout: sw[128][260] | hsm[2][2][256] | gsm[256]
    float* sw  = smem;                         // W rows, pitch 260 (conflict-free)
    const int HSM = 128 * 260;
    float* hsm = smem + HSM;                   // h replica [buf][lb][k]
    float* gsm = smem + HSM + 1024;            // gate exchange

    const int tid = threadIdx.x;               // 0..255
    const int bid = blockIdx.x;                // 0..127
    const int g   = bid >> 3;                  // cluster (group)
    const int r   = bid & 7;                   // rank in cluster
    const int rl  = tid >> 1;                  // row_local 0..127
    const int lb  = tid & 1;                   // local batch 0/1
    const int grow = (rl >> 5) * 256 + r * 32 + (rl & 31);  // global gate row
    const int bglob = 2 * g + lb;
    const uint32_t sb = smem_u32(smem);

    // load this CTA's 128 W_hh rows into smem (once)
    for (int i = tid; i < 128 * 256; i += 256) {
        int row = i >> 8, k = i & 255;
        int grr = 256 * (row >> 5) + 32 * r + (row & 31);
        sw[row * 260 + k] = Whh[(size_t)grr * 256 + k];
    }

    // state owners: tid < 64 -> (jj_o = tid>>1, b_o = tid&1)
    const int jj_o = tid >> 1;
    const int b_o  = tid & 1;
    const int j_o  = 32 * r + jj_o;            // global unit
    const int bg_o = 2 * g + b_o;

    float c_reg = 0.f, h_reg = 0.f;
    int len_b = 0;
    if (tid < 64) {
        h_reg = h0[bg_o * 256 + j_o];
        c_reg = c0[bg_o * 256 + j_o];
        len_b = g_len[bg_o];
        // broadcast initial h into buf0 of every CTA in the cluster
        uint32_t laddr = sb + (uint32_t)(HSM + 0 * 512 + b_o * 256 + j_o) * 4u;
#pragma unroll
        for (int c = 0; c < CPG; c++) st_remote_f32(laddr, c, h_reg);
    }
    __syncthreads();
    CLUSTER_ARRIVE();          // phase 0: init h writes released

    for (int t = 0; t < TT; t++) {
        // prefetch xg before the wait (hide L2/DRAM behind barrier)
        float xgv = __ldg(&g_xg[(size_t)t * 32768 + grow * 32 + bglob]);

        CLUSTER_WAIT();        // acquire: h[t] replica complete in local smem

        // dot: thread (rl, lb): gates[grow][bglob] = xg + W_row . h[lb]
        float a = 0.f;
        {
            const float4* wr = (const float4*)&sw[rl * 260];
            const float4* hr = (const float4*)&hsm[(t & 1) * 512 + lb * 256];
#pragma unroll 16
            for (int k4 = 0; k4 < 64; k4++) {
                float4 wv = wr[k4];
                float4 hv = hr[k4];
                a += wv.x * hv.x; a += wv.y * hv.y;
                a += wv.z * hv.z; a += wv.w * hv.w;
            }
        }
        gsm[tid] = a + xgv;    // gsm[rl*2 + lb]
        __syncthreads();

        float hs_val = 0.f, cs_val = 0.f;
        if (tid < 64) {
            float gi = gsm[(jj_o) * 2 + b_o];            // G=0
            float gf = gsm[(32 + jj_o) * 2 + b_o];       // G=1
            float gg = gsm[(64 + jj_o) * 2 + b_o];       // G=2
            float go = gsm[(96 + jj_o) * 2 + b_o];       // G=3
            float i_ = 1.f / (1.f + __expf(-gi));
            float f_ = 1.f / (1.f + __expf(-gf));
            float g_ = tanhf(gg);
            float o_ = 1.f / (1.f + __expf(-go));
            float cn = f_ * c_reg + i_ * g_;
            float hn = o_ * tanhf(cn);
            if (t < len_b) { c_reg = cn; h_reg = hn; }
            // push h[t+1] into buf[(t+1)&1] of every CTA in the cluster
            uint32_t laddr = sb + (uint32_t)(HSM + ((t + 1) & 1) * 512 + b_o * 256 + j_o) * 4u;
#pragma unroll
            for (int c = 0; c < CPG; c++) st_remote_f32(laddr, c, h_reg);
            hs_val = h_reg; cs_val = c_reg;
        }
        __syncthreads();
        CLUSTER_ARRIVE();      // release h[t+1] writes; peers unblock at next wait

        // output stores inside the barrier window (host-consumed only)
        if (tid < 64) {
            int oidx = t * 8192 + bg_o * 256 + j_o;
            hs_out[oidx] = hs_val;
            if (cs_out) cs_out[oidx] = cs_val;
        }
    }

    CLUSTER_WAIT();            // balance final phase
    if (tid < 64) {
        hT_out[bg_o * 256 + j_o] = h_reg;
        cT_out[bg_o * 256 + j_o] = c_reg;
    }
}

// ---------------- launch ----------------
extern "C" void kernel_launch(void* const* d_in, const int* in_sizes, int n_in,
                              void* d_out, int out_size)
{
    const float* x        = (const float*)d_in[0];
    const int*   lenw     = (const int*)d_in[1];   // dtype detected on device
    const float* h0       = (const float*)d_in[2];
    const float* c0       = (const float*)d_in[3];
    const float* Wih0     = (const float*)d_in[4];
    const float* Whh0     = (const float*)d_in[5];
    const float* b0v      = (const float*)d_in[6];
    const float* Wih1     = (const float*)d_in[7];
    const float* Whh1     = (const float*)d_in[8];
    const float* b1v      = (const float*)d_in[9];
    float* out = (float*)d_out;

    float* xg_p = nullptr;
    float* hs0_p = nullptr;
    cudaGetSymbolAddress((void**)&xg_p, g_xg);
    cudaGetSymbolAddress((void**)&hs0_p, g_hs0);

    const size_t SEQ = (size_t)TT * BB * HH;   // 16,777,216
    float* hs_final = out;                     // [T][B][H]
    float* cs_final = out + SEQ;               // [T][B][H]
    float* hT = out + 2 * SEQ;                 // [2][B][H]
    float* cT = out + 2 * SEQ + 2 * BB * HH;   // [2][B][H]

    // dynamic smem for lstm_rec: (128*260 + 2*2*256 + 256) floats = 138,240 B
    const int rec_smem = (128 * 260 + 2 * 2 * 256 + 256) * (int)sizeof(float);
    cudaFuncSetAttribute(lstm_rec, cudaFuncAttributeMaxDynamicSharedMemorySize, rec_smem);

    dim3 ggrid(1024, 16);

    norm_lengths<<<1, 32>>>(lenw);

    // layer 0
    xg_gemm<<<ggrid, 256>>>(x, Wih0, b0v, xg_p);
    lstm_rec<<<GRID_R, 256, rec_smem>>>(h0, c0, Whh0,
                                        hs0_p, nullptr, hT, cT);
    // layer 1 (input = layer-0 hidden states)
    xg_gemm<<<ggrid, 256>>>(hs0_p, Wih1, b1v, xg_p);
    lstm_rec<<<GRID_R, 256, rec_smem>>>(h0 + BB * HH, c0 + BB * HH, Whh1,
                                        hs_final, cs_final, hT + BB * HH, cT + BB * HH);
}

// round 15
// speedup vs baseline: 1.6617x; 1.6617x over previous
#include <cuda_runtime.h>
#include <cstdint>

#define TT 2048
#define BB 32
#define HH 256
#define G4H 1024
#define GRID_R 128
#define CPG 8          // CTAs per group
#define NGRP 16        // groups (2 batches each)

// ---------------- scratch (static device allocations; no cudaMalloc) ----------------
__device__ float g_xg[(size_t)TT * G4H * BB];     // [t][gate_row][b]  256 MB
__device__ float g_hs0[(size_t)TT * BB * HH];     // layer-0 hidden outputs, 64 MB
__device__ float g_hx[NGRP][2][2][HH];            // h exchange [group][buf][lb][j]
__device__ unsigned g_gctr[2][NGRP][32];          // per-layer per-group counters (128B lines)
__device__ unsigned g_done[2];                    // per-layer reset handshake
__device__ int g_len[BB];                         // normalized lengths (int32)

// morally-strong memory helpers (gpu scope)
__device__ __forceinline__ void arrive_release(unsigned* p) {
    asm volatile("red.release.gpu.global.add.u32 [%0], %1;" :: "l"(p), "r"(1u) : "memory");
}
__device__ __forceinline__ unsigned ld_relaxed(const unsigned* p) {
    unsigned v;
    asm volatile("ld.relaxed.gpu.global.u32 %0, [%1];" : "=r"(v) : "l"(p) : "memory");
    return v;
}

// ---------------- lengths normalization: handles int32 OR int64 input buffer ----------
__global__ void norm_lengths(const int* __restrict__ lenw)
{
    int i = threadIdx.x;            // 0..31
    int is64 = (lenw[1] == 0);
    int v = is64 ? lenw[2 * i] : lenw[i];
    g_len[i] = v;
}

// ---------------- input-projection GEMM: out[t][row][b] = X @ W^T + bias ----------------
// X: [T*B][256] row-major, W: [1024][256], out: [T][1024][32]
// 128x128 tile, 8x8 register blocking, K-step 32, transposed smem, reg-prefetch.
__global__ __launch_bounds__(256) void xg_gemm(const float* __restrict__ X,
                                               const float* __restrict__ W,
                                               const float* __restrict__ bias,
                                               float* __restrict__ out)
{
    __shared__ float ws[32][132];   // [k][m_row]
    __shared__ float xs[32][132];   // [k][tb]
    const int tid = threadIdx.x;
    const int tx = tid & 15;        // tb octet
    const int ty = tid >> 4;        // row octet
    const int n0 = blockIdx.x * 128;  // tb tile base
    const int m0 = blockIdx.y * 128;  // row tile base
    const int lrow = tid >> 3;      // 0..31: row-within-32-chunk for loads
    const int lkq  = tid & 7;       // k-quad for loads

    float acc[8][8];
#pragma unroll
    for (int i = 0; i < 8; i++)
#pragma unroll
        for (int j = 0; j < 8; j++) acc[i][j] = 0.f;

    float4 wreg[4], xreg[4];
    // initial K-slab load (kt = 0)
#pragma unroll
    for (int p = 0; p < 4; p++) {
        wreg[p] = *(const float4*)&W[(size_t)(m0 + lrow + 32 * p) * 256 + lkq * 4];
        xreg[p] = *(const float4*)&X[(size_t)(n0 + lrow + 32 * p) * 256 + lkq * 4];
    }

    for (int kt = 0; kt < 256; kt += 32) {
        // store current slab to smem (transposed)
#pragma unroll
        for (int p = 0; p < 4; p++) {
            int row = lrow + 32 * p;
            ws[lkq * 4 + 0][row] = wreg[p].x;
            ws[lkq * 4 + 1][row] = wreg[p].y;
            ws[lkq * 4 + 2][row] = wreg[p].z;
            ws[lkq * 4 + 3][row] = wreg[p].w;
            xs[lkq * 4 + 0][row] = xreg[p].x;
            xs[lkq * 4 + 1][row] = xreg[p].y;
            xs[lkq * 4 + 2][row] = xreg[p].z;
            xs[lkq * 4 + 3][row] = xreg[p].w;
        }
        __syncthreads();

        // prefetch next slab into registers (hidden under compute)
        if (kt + 32 < 256) {
#pragma unroll
            for (int p = 0; p < 4; p++) {
                wreg[p] = *(const float4*)&W[(size_t)(m0 + lrow + 32 * p) * 256 + kt + 32 + lkq * 4];
                xreg[p] = *(const float4*)&X[(size_t)(n0 + lrow + 32 * p) * 256 + kt + 32 + lkq * 4];
            }
        }

        // 8x8 microkernel over 32 ks
#pragma unroll
        for (int k = 0; k < 32; k++) {
            float a[8], bfr[8];
            *(float4*)&a[0]   = *(const float4*)&ws[k][ty * 8];
            *(float4*)&a[4]   = *(const float4*)&ws[k][ty * 8 + 4];
            *(float4*)&bfr[0] = *(const float4*)&xs[k][tx * 8];
            *(float4*)&bfr[4] = *(const float4*)&xs[k][tx * 8 + 4];
#pragma unroll
            for (int i = 0; i < 8; i++)
#pragma unroll
                for (int j = 0; j < 8; j++) acc[i][j] += a[i] * bfr[j];
        }
        __syncthreads();
    }

    // epilogue: tb octet never crosses a b=32 boundary (tx*8 aligned)
    const int tbb = n0 + tx * 8;
    const int t = tbb >> 5;
    const int b0 = tbb & 31;
#pragma unroll
    for (int i = 0; i < 8; i++) {
        int row = m0 + ty * 8 + i;
        float bv = bias[row];
        float4 v0 = make_float4(acc[i][0] + bv, acc[i][1] + bv, acc[i][2] + bv, acc[i][3] + bv);
        float4 v1 = make_float4(acc[i][4] + bv, acc[i][5] + bv, acc[i][6] + bv, acc[i][7] + bv);
        *(float4*)&out[(size_t)t * 32768 + row * 32 + b0]     = v0;
        *(float4*)&out[(size_t)t * 32768 + row * 32 + b0 + 4] = v1;
    }
}

// ---------------- persistent recurrent kernel: GROUP-LOCAL sync (round-10, banked) ----
__global__ __launch_bounds__(256) void lstm_rec(
    const int layer,
    const float* __restrict__ h0,        // [B][H] slice for this layer
    const float* __restrict__ c0,
    const float* __restrict__ Whh,       // [1024][256]
    float* __restrict__ hs_out,          // [T][B][H]
    float* __restrict__ cs_out,          // [T][B][H] or nullptr
    float* __restrict__ hT_out,          // [B][H]
    float* __restrict__ cT_out)
{
    extern __shared__ float smem[];
    // layout: sw[128][260] | hsm[2][260] | gsm[256]
    float* sw  = smem;                    // W rows, pitch 260 (conflict-free)
    float* hsm = smem + 128 * 260;        // staged h, pitch 260
    float* gsm = hsm + 2 * 260;           // gate exchange, gsm[rl*2+lb]

    const int tid = threadIdx.x;          // 0..255
    const int bid = blockIdx.x;           // 0..127
    const int g   = bid >> 3;             // group
    const int r   = bid & 7;              // rank in group
    const int rl  = tid >> 1;             // row_local 0..127
    const int lb  = tid & 1;              // local batch 0/1
    const int grow = (rl >> 5) * 256 + r * 32 + (rl & 31);  // global gate row
    const int bglob = 2 * g + lb;

    // load this CTA's 128 W_hh rows into smem (once)
    for (int i = tid; i < 128 * 256; i += 256) {
        int row = i >> 8, k = i & 255;
        int grr = 256 * (row >> 5) + 32 * r + (row & 31);
        sw[row * 260 + k] = Whh[(size_t)grr * 256 + k];
    }

    // state owners: tid < 64 -> (jj_o = tid>>1, b_o = tid&1)
    const int jj_o = tid >> 1;            // unit within CTA's 32 (valid tid<64)
    const int b_o  = tid & 1;
    const int j_o  = 32 * r + jj_o;       // global unit
    const int bg_o = 2 * g + b_o;

    float c_reg = 0.f, h_reg = 0.f;
    int len_b = 0;
    if (tid < 64) {
        h_reg = h0[bg_o * 256 + j_o];
        c_reg = c0[bg_o * 256 + j_o];
        len_b = g_len[bg_o];
        __stcg(&g_hx[g][0][b_o][j_o], h_reg);
    }
    __syncthreads();
    if (tid == 0) arrive_release(&g_gctr[layer][g][0]);

    unsigned target = CPG;

    for (int t = 0; t < TT; t++) {
        // prefetch xg (independent of barrier)
        float xgv = __ldg(&g_xg[(size_t)t * 32768 + grow * 32 + bglob]);

        // group barrier: 8 arrivals, everyone polls own group's line
        if (tid == 0) {
            const unsigned* cp = &g_gctr[layer][g][0];
            while (ld_relaxed(cp) < target) { }
            __threadfence();   // acquire: counter obs -> peer h visibility
        }
        __syncthreads();
        target += CPG;

        // stage group h (2 batches x 256) into smem
        if (tid < 128) {
            const float4* hb = (const float4*)&g_hx[g][t & 1][0][0];
            float4 v = __ldcg(&hb[tid]);
            int b_ = tid >> 6, k4 = tid & 63;
            *(float4*)&hsm[b_ * 260 + k4 * 4] = v;
        }
        __syncthreads();

        // dot: thread (rl, lb): gates[grow][bglob] = xg + W_row . h[lb]
        float a = 0.f;
        {
            const float4* wr = (const float4*)&sw[rl * 260];
            const float4* hr = (const float4*)&hsm[lb * 260];
#pragma unroll 16
            for (int k4 = 0; k4 < 64; k4++) {
                float4 wv = wr[k4];
                float4 hv = hr[k4];
                a += wv.x * hv.x; a += wv.y * hv.y;
                a += wv.z * hv.z; a += wv.w * hv.w;
            }
        }
        gsm[tid] = a + xgv;               // gsm[rl*2 + lb]
        __syncthreads();

        float hs_val = 0.f, cs_val = 0.f;
        if (tid < 64) {
            float gi = gsm[(jj_o) * 2 + b_o];            // G=0 rows
            float gf = gsm[(32 + jj_o) * 2 + b_o];       // G=1
            float gg = gsm[(64 + jj_o) * 2 + b_o];       // G=2
            float go = gsm[(96 + jj_o) * 2 + b_o];       // G=3
            float i_ = 1.f / (1.f + __expf(-gi));
            float f_ = 1.f / (1.f + __expf(-gf));
            float g_ = tanhf(gg);
            float o_ = 1.f / (1.f + __expf(-go));
            float cn = f_ * c_reg + i_ * g_;
            float hn = o_ * tanhf(cn);
            if (t < len_b) { c_reg = cn; h_reg = hn; }
            __stcg(&g_hx[g][(t + 1) & 1][b_o][j_o], h_reg);
            hs_val = h_reg; cs_val = c_reg;
        }
        __syncthreads();
        if (tid == 0) arrive_release(&g_gctr[layer][g][0]);

        // output stores AFTER arrival (host-consumed only; overlap peers' wait)
        if (tid < 64) {
            int oidx = t * 8192 + bg_o * 256 + j_o;
            hs_out[oidx] = hs_val;
            if (cs_out) cs_out[oidx] = cs_val;
        }
    }

    if (tid < 64) {
        hT_out[bg_o * 256 + j_o] = h_reg;
        cT_out[bg_o * 256 + j_o] = c_reg;
    }

    // reset handshake so graph replays start from clean counters.
    // Fence between final arrival atomic and g_done atomic (verified round-7 fix).
    __syncthreads();
    if (tid == 0) {
        __threadfence();
        unsigned d = atomicAdd(&g_done[layer], 1);
        if (d == GRID_R - 1) {
#pragma unroll
            for (int i = 0; i < NGRP; i++) g_gctr[layer][i][0] = 0;
            __threadfence();
            g_done[layer] = 0;
        }
    }
}

// ---------------- launch ----------------
extern "C" void kernel_launch(void* const* d_in, const int* in_sizes, int n_in,
                              void* d_out, int out_size)
{
    const float* x        = (const float*)d_in[0];
    const int*   lenw     = (const int*)d_in[1];   // dtype detected on device
    const float* h0       = (const float*)d_in[2];
    const float* c0       = (const float*)d_in[3];
    const float* Wih0     = (const float*)d_in[4];
    const float* Whh0     = (const float*)d_in[5];
    const float* b0v      = (const float*)d_in[6];
    const float* Wih1     = (const float*)d_in[7];
    const float* Whh1     = (const float*)d_in[8];
    const float* b1v      = (const float*)d_in[9];
    float* out = (float*)d_out;

    float* xg_p = nullptr;
    float* hs0_p = nullptr;
    cudaGetSymbolAddress((void**)&xg_p, g_xg);
    cudaGetSymbolAddress((void**)&hs0_p, g_hs0);

    const size_t SEQ = (size_t)TT * BB * HH;   // 16,777,216
    float* hs_final = out;                     // [T][B][H]
    float* cs_final = out + SEQ;               // [T][B][H]
    float* hT = out + 2 * SEQ;                 // [2][B][H]
    float* cT = out + 2 * SEQ + 2 * BB * HH;   // [2][B][H]

    // dynamic smem for lstm_rec: (128*260 + 2*260 + 256) floats
    const int rec_smem = (128 * 260 + 2 * 260 + 256) * (int)sizeof(float);
    cudaFuncSetAttribute(lstm_rec, cudaFuncAttributeMaxDynamicSharedMemorySize, rec_smem);

    dim3 ggrid(512, 8);    // 128-wide tb tiles x 128-wide row tiles

    norm_lengths<<<1, 32>>>(lenw);

    // layer 0
    xg_gemm<<<ggrid, 256>>>(x, Wih0, b0v, xg_p);
    lstm_rec<<<GRID_R, 256, rec_smem>>>(0, h0, c0, Whh0,
                                        hs0_p, nullptr, hT, cT);
    // layer 1 (input = layer-0 hidden states)
    xg_gemm<<<ggrid, 256>>>(hs0_p, Wih1, b1v, xg_p);
    lstm_rec<<<GRID_R, 256, rec_smem>>>(1, h0 + BB * HH, c0 + BB * HH, Whh1,
                                        hs_final, cs_final, hT + BB * HH, cT + BB * HH);
}